// round 1
// baseline (speedup 1.0000x reference)
#include <cuda_runtime.h>

#define S_LEN 4096
#define HID 2048
#define NLAYERS 4

// ---------------- scan (recurrence) config ----------------
#define GBLK 128          // persistent blocks; must all be co-resident (<= #SMs)
#define ROWS_PER_BLK 16   // 2048 / 128
#define SCAN_TPB 512
#define KPT 64            // k-elements per thread: 2048 / (512/16)

// ---------------- scratch (static device globals; no cudaMalloc allowed) ----
__device__ float g_xw[S_LEN * HID];     // input projection for current layer
__device__ float g_buf0[S_LEN * HID];   // layer output ping
__device__ float g_buf1[S_LEN * HID];   // layer output pong
__device__ float g_h[2][HID];           // hidden-state ping-pong
__device__ unsigned int g_bar;          // grid barrier counter

// ---------------------------------------------------------------------------
// reset: zero barrier counter + hidden state before each layer's scan
// ---------------------------------------------------------------------------
__global__ void reset_kernel() {
    int i = threadIdx.x;
    if (i == 0) g_bar = 0u;
    float* h = &g_h[0][0];
    for (int j = i; j < 2 * HID; j += blockDim.x) h[j] = 0.0f;
}

// ---------------------------------------------------------------------------
// GEMM: C[i,j] = sum_k A[i,k] * B[j,k]
// A: [M x K] row-major, B: [N x K] row-major (both K-contiguous), C: [M x N]
// M=4096, N=K=2048. 128x128 block tile, BK=8, 256 threads, 8x8 per thread.
// ---------------------------------------------------------------------------
__global__ void __launch_bounds__(256) gemm_kernel(const float* __restrict__ A,
                                                   const float* __restrict__ B,
                                                   float* __restrict__ C) {
    const int K = HID;
    const int N = HID;
    __shared__ float As[8][128];
    __shared__ float Bs[8][128];

    const int tid  = threadIdx.x;
    const int tx   = tid & 15;   // 0..15  -> N direction
    const int ty   = tid >> 4;   // 0..15  -> M direction
    const int lrow = tid >> 1;   // 0..127 loader row
    const int lk   = (tid & 1) * 4;

    const float* Ap = A + (size_t)(blockIdx.y * 128 + lrow) * K + lk;
    const float* Bp = B + (size_t)(blockIdx.x * 128 + lrow) * K + lk;

    float acc[8][8];
#pragma unroll
    for (int i = 0; i < 8; i++)
#pragma unroll
        for (int j = 0; j < 8; j++) acc[i][j] = 0.0f;

    for (int k0 = 0; k0 < K; k0 += 8) {
        float4 av = *(const float4*)(Ap + k0);
        float4 bv = *(const float4*)(Bp + k0);
        __syncthreads();  // protect SMEM from previous iter's readers
        As[lk + 0][lrow] = av.x;
        As[lk + 1][lrow] = av.y;
        As[lk + 2][lrow] = av.z;
        As[lk + 3][lrow] = av.w;
        Bs[lk + 0][lrow] = bv.x;
        Bs[lk + 1][lrow] = bv.y;
        Bs[lk + 2][lrow] = bv.z;
        Bs[lk + 3][lrow] = bv.w;
        __syncthreads();

#pragma unroll
        for (int kk = 0; kk < 8; kk++) {
            float4 a0 = *(const float4*)&As[kk][ty * 8];
            float4 a1 = *(const float4*)&As[kk][ty * 8 + 4];
            float4 b0 = *(const float4*)&Bs[kk][tx * 8];
            float4 b1 = *(const float4*)&Bs[kk][tx * 8 + 4];
            float a[8] = {a0.x, a0.y, a0.z, a0.w, a1.x, a1.y, a1.z, a1.w};
            float b[8] = {b0.x, b0.y, b0.z, b0.w, b1.x, b1.y, b1.z, b1.w};
#pragma unroll
            for (int i = 0; i < 8; i++)
#pragma unroll
                for (int j = 0; j < 8; j++) acc[i][j] = fmaf(a[i], b[j], acc[i][j]);
        }
    }

#pragma unroll
    for (int i = 0; i < 8; i++) {
        float* Cp = C + (size_t)(blockIdx.y * 128 + ty * 8 + i) * N +
                    blockIdx.x * 128 + tx * 8;
        *(float4*)(Cp + 0) = make_float4(acc[i][0], acc[i][1], acc[i][2], acc[i][3]);
        *(float4*)(Cp + 4) = make_float4(acc[i][4], acc[i][5], acc[i][6], acc[i][7]);
    }
}

// ---------------------------------------------------------------------------
// Persistent recurrence kernel: h_t = relu(xw_t + W_hh @ h_{t-1})
// 128 blocks x 512 threads. Each block owns 16 output rows; W_hh slice lives
// entirely in registers (64 floats/thread). h broadcast via global (L2, .cg
// loads — L1 is NOT coherent across blocks within a launch). Grid-wide
// spin-barrier on an atomic counter per timestep.
// ---------------------------------------------------------------------------
__global__ void __launch_bounds__(SCAN_TPB, 1) scan_kernel(
    const float* __restrict__ xw, const float* __restrict__ whh,
    float* __restrict__ y, float* __restrict__ hlast) {
    __shared__ float hbuf[HID];
    __shared__ float part[16][ROWS_PER_BLK];

    const int tid  = threadIdx.x;
    const int row  = tid & 15;   // output row within block
    const int kg   = tid >> 4;   // 0..31 k-group
    const int k0   = kg * KPT;
    const int rowG = blockIdx.x * ROWS_PER_BLK + row;
    const int warp = tid >> 5;   // 0..15
    const int lane = tid & 31;

    // W_hh slice -> registers (one-time, 16 MB total across chip)
    float w[KPT];
    {
        const float* wr = whh + (size_t)rowG * HID + k0;
#pragma unroll
        for (int i = 0; i < KPT; i += 4) {
            float4 v = *(const float4*)(wr + i);
            w[i] = v.x; w[i + 1] = v.y; w[i + 2] = v.z; w[i + 3] = v.w;
        }
    }

    int p = 0;
    for (int t = 0; t < S_LEN; ++t) {
        // broadcast h_{t-1}: 2048 floats, one float4 per thread, L2-only load
        float4 hv4 = __ldcg((const float4*)&g_h[p][tid * 4]);
        *(float4*)&hbuf[tid * 4] = hv4;
        __syncthreads();

        // partial dot product: 64 MACs from register-resident W
        float a0 = 0.f, a1 = 0.f, a2 = 0.f, a3 = 0.f;
#pragma unroll
        for (int i = 0; i < KPT; i += 4) {
            float4 hv = *(const float4*)&hbuf[k0 + i];
            a0 = fmaf(w[i + 0], hv.x, a0);
            a1 = fmaf(w[i + 1], hv.y, a1);
            a2 = fmaf(w[i + 2], hv.z, a2);
            a3 = fmaf(w[i + 3], hv.w, a3);
        }
        float acc = (a0 + a1) + (a2 + a3);

        // combine the two k-groups living in one warp
        acc += __shfl_down_sync(0xffffffffu, acc, 16);
        if (lane < 16) part[warp][lane] = acc;  // lane == row here
        __syncthreads();

        // final reduce + bias + relu + publish (16 threads)
        if (tid < ROWS_PER_BLK) {
            float s = 0.f;
#pragma unroll
            for (int q = 0; q < 16; q++) s += part[q][tid];
            int col  = blockIdx.x * ROWS_PER_BLK + tid;
            float hv = s + __ldg(&xw[(size_t)t * HID + col]);
            hv = fmaxf(hv, 0.0f);
            g_h[p ^ 1][col]         = hv;
            y[(size_t)t * HID + col] = hv;
            if (hlast != nullptr && t == S_LEN - 1) hlast[col] = hv;
            __threadfence();  // writers fence BEFORE the barrier arrival
        }
        __syncthreads();

        // grid barrier (monotonic counter; reset_kernel zeroes it per layer)
        if (tid == 0) {
            unsigned arrived = atomicAdd(&g_bar, 1u) + 1u;
            unsigned target  = (unsigned)(t + 1) * (unsigned)GBLK;
            if (arrived < target) {
                while (*((volatile unsigned*)&g_bar) < target) { }
            }
            __threadfence();
        }
        __syncthreads();
        p ^= 1;
    }
}

// ---------------------------------------------------------------------------
// host launcher (graph-capturable: kernel launches only)
// inputs: d_in[0]=input [1,S,H] f32, d_in[1]=weight_ih [4,H,H], d_in[2]=weight_hh [4,H,H]
// output: d_out = concat(output [S*H], h_last [H])
// ---------------------------------------------------------------------------
extern "C" void kernel_launch(void* const* d_in, const int* in_sizes, int n_in,
                              void* d_out, int out_size) {
    const float* x0  = (const float*)d_in[0];
    const float* wih = (const float*)d_in[1];
    const float* whh = (const float*)d_in[2];
    float* out = (float*)d_out;

    void *p_xw, *p_b0, *p_b1;
    cudaGetSymbolAddress(&p_xw, g_xw);
    cudaGetSymbolAddress(&p_b0, g_buf0);
    cudaGetSymbolAddress(&p_b1, g_buf1);
    float* bufs[2] = {(float*)p_b0, (float*)p_b1};

    float* hlast = (out_size >= S_LEN * HID + HID) ? out + (size_t)S_LEN * HID
                                                   : nullptr;

    const float* x = x0;
    dim3 ggrid(HID / 128, S_LEN / 128);
    for (int L = 0; L < NLAYERS; ++L) {
        reset_kernel<<<1, 512>>>();
        gemm_kernel<<<ggrid, 256>>>(x, wih + (size_t)L * HID * HID, (float*)p_xw);
        float* yout = (L == NLAYERS - 1) ? out : bufs[L & 1];
        scan_kernel<<<GBLK, SCAN_TPB>>>((const float*)p_xw,
                                        whh + (size_t)L * HID * HID, yout,
                                        (L == NLAYERS - 1) ? hlast : nullptr);
        x = yout;
    }
}

// round 4
// speedup vs baseline: 1.1341x; 1.1341x over previous
#include <cuda_runtime.h>

#define S_LEN 4096
#define HID 2048
#define NLAYERS 4

// ---------------- scan (recurrence) config ----------------
#define GBLK 128          // persistent blocks; all co-resident (proven in R1)
#define ROWS_PER_BLK 16   // 2048 / 128
#define SCAN_TPB 512
#define KPT 64            // k-elements per thread: 2048 / (512/16)

// ---------------- GEMM config ----------------
#define BK 16

// ---------------- scratch (static device globals) ----------
__device__ float g_xw[S_LEN * HID];     // input projection for current layer
__device__ float g_buf0[S_LEN * HID];   // layer output ping
__device__ float g_buf1[S_LEN * HID];   // layer output pong
__device__ float g_h[2][HID];           // hidden-state ping-pong
__device__ unsigned int g_bar;          // grid barrier counter

// ---------------- f32x2 helpers (numerically = two independent IEEE fmas) --
__device__ __forceinline__ void fma2(unsigned long long& d, unsigned long long a,
                                     unsigned long long b, unsigned long long c) {
    asm("fma.rn.f32x2 %0, %1, %2, %3;" : "=l"(d) : "l"(a), "l"(b), "l"(c));
}
__device__ __forceinline__ unsigned long long pack2(float lo, float hi) {
    unsigned long long r;
    asm("mov.b64 %0, {%1, %2};" : "=l"(r) : "f"(lo), "f"(hi));
    return r;
}
__device__ __forceinline__ float2 unpack2(unsigned long long v) {
    float2 f;
    asm("mov.b64 {%0, %1}, %2;" : "=f"(f.x), "=f"(f.y) : "l"(v));
    return f;
}

// ---------------------------------------------------------------------------
// reset (verbatim from passing R1): zero barrier counter + hidden state
// ---------------------------------------------------------------------------
__global__ void reset_kernel() {
    int i = threadIdx.x;
    if (i == 0) g_bar = 0u;
    float* h = &g_h[0][0];
    for (int j = i; j < 2 * HID; j += blockDim.x) h[j] = 0.0f;
}

// ---------------------------------------------------------------------------
// GEMM: C[i,j] = sum_k A[i,k] * B[j,k]; A:[M,K], B:[N,K] K-contig, C:[M,N]
// 128x128 tile, BK=16, double-buffered SMEM, 256 threads, 8x8/thread, f32x2.
// Layout As[stage][k][row] (transpose-on-store) -> conflict-free compute reads.
// ---------------------------------------------------------------------------
__global__ void __launch_bounds__(256, 2) gemm_kernel(const float* __restrict__ A,
                                                      const float* __restrict__ B,
                                                      float* __restrict__ C) {
    const int K = HID;
    const int N = HID;
    __shared__ float As[2][BK][128];
    __shared__ float Bs[2][BK][128];

    const int tid  = threadIdx.x;
    const int tx   = tid & 15;   // N direction
    const int ty   = tid >> 4;   // M direction
    const int lrow = tid >> 1;   // 0..127 loader row
    const int lk   = (tid & 1) * 8;  // 0 or 8: which 8-k chunk of the row

    const float* Ap = A + (size_t)(blockIdx.y * 128 + lrow) * K + lk;
    const float* Bp = B + (size_t)(blockIdx.x * 128 + lrow) * K + lk;

    unsigned long long acc2[8][4];
    const unsigned long long z2 = pack2(0.0f, 0.0f);
#pragma unroll
    for (int i = 0; i < 8; i++)
#pragma unroll
        for (int j = 0; j < 4; j++) acc2[i][j] = z2;

    // ---- stage 0 load + store ----
    {
        float4 a0 = *(const float4*)(Ap);
        float4 a1 = *(const float4*)(Ap + 4);
        float4 b0 = *(const float4*)(Bp);
        float4 b1 = *(const float4*)(Bp + 4);
        As[0][lk + 0][lrow] = a0.x; As[0][lk + 1][lrow] = a0.y;
        As[0][lk + 2][lrow] = a0.z; As[0][lk + 3][lrow] = a0.w;
        As[0][lk + 4][lrow] = a1.x; As[0][lk + 5][lrow] = a1.y;
        As[0][lk + 6][lrow] = a1.z; As[0][lk + 7][lrow] = a1.w;
        Bs[0][lk + 0][lrow] = b0.x; Bs[0][lk + 1][lrow] = b0.y;
        Bs[0][lk + 2][lrow] = b0.z; Bs[0][lk + 3][lrow] = b0.w;
        Bs[0][lk + 4][lrow] = b1.x; Bs[0][lk + 5][lrow] = b1.y;
        Bs[0][lk + 6][lrow] = b1.z; Bs[0][lk + 7][lrow] = b1.w;
    }
    __syncthreads();

    int cur = 0;
    for (int k0 = BK; k0 <= K; k0 += BK) {
        // prefetch next stage (skipped on final iteration)
        float4 na0, na1, nb0, nb1;
        const bool more = (k0 < K);
        if (more) {
            na0 = *(const float4*)(Ap + k0);
            na1 = *(const float4*)(Ap + k0 + 4);
            nb0 = *(const float4*)(Bp + k0);
            nb1 = *(const float4*)(Bp + k0 + 4);
        }

        // compute on current stage
#pragma unroll
        for (int kk = 0; kk < BK; kk++) {
            float4 a0 = *(const float4*)&As[cur][kk][ty * 8];
            float4 a1 = *(const float4*)&As[cur][kk][ty * 8 + 4];
            ulonglong2 bp0 = *(const ulonglong2*)&Bs[cur][kk][tx * 8];
            ulonglong2 bp1 = *(const ulonglong2*)&Bs[cur][kk][tx * 8 + 4];
            float a[8] = {a0.x, a0.y, a0.z, a0.w, a1.x, a1.y, a1.z, a1.w};
#pragma unroll
            for (int i = 0; i < 8; i++) {
                unsigned long long aa = pack2(a[i], a[i]);
                fma2(acc2[i][0], aa, bp0.x, acc2[i][0]);
                fma2(acc2[i][1], aa, bp0.y, acc2[i][1]);
                fma2(acc2[i][2], aa, bp1.x, acc2[i][2]);
                fma2(acc2[i][3], aa, bp1.y, acc2[i][3]);
            }
        }

        if (more) {
            int nxt = cur ^ 1;
            As[nxt][lk + 0][lrow] = na0.x; As[nxt][lk + 1][lrow] = na0.y;
            As[nxt][lk + 2][lrow] = na0.z; As[nxt][lk + 3][lrow] = na0.w;
            As[nxt][lk + 4][lrow] = na1.x; As[nxt][lk + 5][lrow] = na1.y;
            As[nxt][lk + 6][lrow] = na1.z; As[nxt][lk + 7][lrow] = na1.w;
            Bs[nxt][lk + 0][lrow] = nb0.x; Bs[nxt][lk + 1][lrow] = nb0.y;
            Bs[nxt][lk + 2][lrow] = nb0.z; Bs[nxt][lk + 3][lrow] = nb0.w;
            Bs[nxt][lk + 4][lrow] = nb1.x; Bs[nxt][lk + 5][lrow] = nb1.y;
            Bs[nxt][lk + 6][lrow] = nb1.z; Bs[nxt][lk + 7][lrow] = nb1.w;
            __syncthreads();
            cur = nxt;
        }
    }

#pragma unroll
    for (int i = 0; i < 8; i++) {
        float* Cp = C + (size_t)(blockIdx.y * 128 + ty * 8 + i) * N +
                    blockIdx.x * 128 + tx * 8;
        float2 c0 = unpack2(acc2[i][0]);
        float2 c1 = unpack2(acc2[i][1]);
        float2 c2 = unpack2(acc2[i][2]);
        float2 c3 = unpack2(acc2[i][3]);
        *(float4*)(Cp + 0) = make_float4(c0.x, c0.y, c1.x, c1.y);
        *(float4*)(Cp + 4) = make_float4(c2.x, c2.y, c3.x, c3.y);
    }
}

// ---------------------------------------------------------------------------
// Persistent recurrence (PROVEN R1 protocol, verbatim except xw prefetch
// hoisted above the work — xw is immutable within a layer).
// h_t = relu(xw_t + W_hh @ h_{t-1}); atomic-counter grid barrier per step.
// ---------------------------------------------------------------------------
__global__ void __launch_bounds__(SCAN_TPB, 1) scan_kernel(
    const float* __restrict__ xw, const float* __restrict__ whh,
    float* __restrict__ y, float* __restrict__ hlast) {
    __shared__ float hbuf[HID];
    __shared__ float part[16][ROWS_PER_BLK];

    const int tid  = threadIdx.x;
    const int row  = tid & 15;
    const int kg   = tid >> 4;
    const int k0   = kg * KPT;
    const int rowG = blockIdx.x * ROWS_PER_BLK + row;
    const int warp = tid >> 5;
    const int lane = tid & 31;
    const int col  = blockIdx.x * ROWS_PER_BLK + tid;  // used when tid<16

    // W_hh slice -> registers (one-time)
    float w[KPT];
    {
        const float* wr = whh + (size_t)rowG * HID + k0;
#pragma unroll
        for (int i = 0; i < KPT; i += 4) {
            float4 v = *(const float4*)(wr + i);
            w[i] = v.x; w[i + 1] = v.y; w[i + 2] = v.z; w[i + 3] = v.w;
        }
    }

    int p = 0;
    for (int t = 0; t < S_LEN; ++t) {
        // prefetch xw early (immutable; hides DRAM/L2 latency off crit path)
        float xwv = 0.0f;
        if (tid < ROWS_PER_BLK) xwv = __ldg(&xw[(size_t)t * HID + col]);

        // broadcast h_{t-1}: one float4 per thread, L2 load
        float4 hv4 = __ldcg((const float4*)&g_h[p][tid * 4]);
        *(float4*)&hbuf[tid * 4] = hv4;
        __syncthreads();

        // partial dot product from register-resident W
        float a0 = 0.f, a1 = 0.f, a2 = 0.f, a3 = 0.f;
#pragma unroll
        for (int i = 0; i < KPT; i += 4) {
            float4 hv = *(const float4*)&hbuf[k0 + i];
            a0 = fmaf(w[i + 0], hv.x, a0);
            a1 = fmaf(w[i + 1], hv.y, a1);
            a2 = fmaf(w[i + 2], hv.z, a2);
            a3 = fmaf(w[i + 3], hv.w, a3);
        }
        float acc = (a0 + a1) + (a2 + a3);

        // combine the two k-groups living in one warp
        acc += __shfl_down_sync(0xffffffffu, acc, 16);
        if (lane < 16) part[warp][lane] = acc;
        __syncthreads();

        // final reduce + relu + publish (16 threads)
        if (tid < ROWS_PER_BLK) {
            float s = 0.f;
#pragma unroll
            for (int q = 0; q < 16; q++) s += part[q][tid];
            float hv = fmaxf(s + xwv, 0.0f);
            g_h[p ^ 1][col]          = hv;
            y[(size_t)t * HID + col] = hv;
            if (hlast != nullptr && t == S_LEN - 1) hlast[col] = hv;
            __threadfence();  // publish h before barrier arrival
        }
        __syncthreads();

        // grid barrier (monotonic counter; reset per layer)
        if (tid == 0) {
            unsigned arrived = atomicAdd(&g_bar, 1u) + 1u;
            unsigned target  = (unsigned)(t + 1) * (unsigned)GBLK;
            if (arrived < target) {
                while (*((volatile unsigned*)&g_bar) < target) { }
            }
            __threadfence();
        }
        __syncthreads();
        p ^= 1;
    }
}

// ---------------------------------------------------------------------------
// host launcher (graph-capturable: kernel launches only)
// ---------------------------------------------------------------------------
extern "C" void kernel_launch(void* const* d_in, const int* in_sizes, int n_in,
                              void* d_out, int out_size) {
    const float* x0  = (const float*)d_in[0];
    const float* wih = (const float*)d_in[1];
    const float* whh = (const float*)d_in[2];
    float* out = (float*)d_out;

    void *p_xw, *p_b0, *p_b1;
    cudaGetSymbolAddress(&p_xw, g_xw);
    cudaGetSymbolAddress(&p_b0, g_buf0);
    cudaGetSymbolAddress(&p_b1, g_buf1);
    float* bufs[2] = {(float*)p_b0, (float*)p_b1};

    float* hlast = (out_size >= S_LEN * HID + HID) ? out + (size_t)S_LEN * HID
                                                   : nullptr;

    const float* x = x0;
    dim3 ggrid(HID / 128, S_LEN / 128);
    for (int L = 0; L < NLAYERS; ++L) {
        reset_kernel<<<1, 512>>>();
        gemm_kernel<<<ggrid, 256>>>(x, wih + (size_t)L * HID * HID, (float*)p_xw);
        float* yout = (L == NLAYERS - 1) ? out : bufs[L & 1];
        scan_kernel<<<GBLK, SCAN_TPB>>>((const float*)p_xw,
                                        whh + (size_t)L * HID * HID, yout,
                                        (L == NLAYERS - 1) ? hlast : nullptr);
        x = yout;
    }
}

// round 5
// speedup vs baseline: 1.2822x; 1.1305x over previous
#include <cuda_runtime.h>

#define S_LEN 4096
#define HID 2048
#define NLAYERS 4

// ---------------- scan (recurrence) config ----------------
#define GBLK 128          // persistent blocks; all co-resident (proven R1/R4)
#define ROWS_PER_BLK 16   // 2048 / 128
#define SCAN_TPB 512
#define KPT 64            // k-elements per thread: 2048 / (512/16)

// ---------------- GEMM config ----------------
#define BK 16

// ---------------- scratch (static device globals) ----------
__device__ float g_xw[S_LEN * HID];     // input projection for current layer
__device__ float g_buf0[S_LEN * HID];   // layer output ping
__device__ float g_buf1[S_LEN * HID];   // layer output pong
__device__ float g_h[2][HID];           // hidden-state ping-pong
__device__ unsigned int g_bar;          // grid barrier counter

// ---------------- f32x2 helpers (PROVEN by passing R4 GEMM) ----------------
__device__ __forceinline__ void fma2(unsigned long long& d, unsigned long long a,
                                     unsigned long long b, unsigned long long c) {
    asm("fma.rn.f32x2 %0, %1, %2, %3;" : "=l"(d) : "l"(a), "l"(b), "l"(c));
}
__device__ __forceinline__ unsigned long long pack2(float lo, float hi) {
    unsigned long long r;
    asm("mov.b64 %0, {%1, %2};" : "=l"(r) : "f"(lo), "f"(hi));
    return r;
}
__device__ __forceinline__ float2 unpack2(unsigned long long v) {
    float2 f;
    asm("mov.b64 {%0, %1}, %2;" : "=f"(f.x), "=f"(f.y) : "l"(v));
    return f;
}

// ---------------------------------------------------------------------------
// reset (verbatim from passing R1/R4): zero barrier counter + hidden state
// ---------------------------------------------------------------------------
__global__ void reset_kernel() {
    int i = threadIdx.x;
    if (i == 0) g_bar = 0u;
    float* h = &g_h[0][0];
    for (int j = i; j < 2 * HID; j += blockDim.x) h[j] = 0.0f;
}

// ---------------------------------------------------------------------------
// GEMM (verbatim from PASSING R4): C[i,j] = sum_k A[i,k]*B[j,k]
// 128x128 tile, BK=16, double-buffered SMEM, 256 threads, 8x8/thread, f32x2.
// ---------------------------------------------------------------------------
__global__ void __launch_bounds__(256, 2) gemm_kernel(const float* __restrict__ A,
                                                      const float* __restrict__ B,
                                                      float* __restrict__ C) {
    const int K = HID;
    const int N = HID;
    __shared__ float As[2][BK][128];
    __shared__ float Bs[2][BK][128];

    const int tid  = threadIdx.x;
    const int tx   = tid & 15;
    const int ty   = tid >> 4;
    const int lrow = tid >> 1;
    const int lk   = (tid & 1) * 8;

    const float* Ap = A + (size_t)(blockIdx.y * 128 + lrow) * K + lk;
    const float* Bp = B + (size_t)(blockIdx.x * 128 + lrow) * K + lk;

    unsigned long long acc2[8][4];
    const unsigned long long z2 = pack2(0.0f, 0.0f);
#pragma unroll
    for (int i = 0; i < 8; i++)
#pragma unroll
        for (int j = 0; j < 4; j++) acc2[i][j] = z2;

    {
        float4 a0 = *(const float4*)(Ap);
        float4 a1 = *(const float4*)(Ap + 4);
        float4 b0 = *(const float4*)(Bp);
        float4 b1 = *(const float4*)(Bp + 4);
        As[0][lk + 0][lrow] = a0.x; As[0][lk + 1][lrow] = a0.y;
        As[0][lk + 2][lrow] = a0.z; As[0][lk + 3][lrow] = a0.w;
        As[0][lk + 4][lrow] = a1.x; As[0][lk + 5][lrow] = a1.y;
        As[0][lk + 6][lrow] = a1.z; As[0][lk + 7][lrow] = a1.w;
        Bs[0][lk + 0][lrow] = b0.x; Bs[0][lk + 1][lrow] = b0.y;
        Bs[0][lk + 2][lrow] = b0.z; Bs[0][lk + 3][lrow] = b0.w;
        Bs[0][lk + 4][lrow] = b1.x; Bs[0][lk + 5][lrow] = b1.y;
        Bs[0][lk + 6][lrow] = b1.z; Bs[0][lk + 7][lrow] = b1.w;
    }
    __syncthreads();

    int cur = 0;
    for (int k0 = BK; k0 <= K; k0 += BK) {
        float4 na0, na1, nb0, nb1;
        const bool more = (k0 < K);
        if (more) {
            na0 = *(const float4*)(Ap + k0);
            na1 = *(const float4*)(Ap + k0 + 4);
            nb0 = *(const float4*)(Bp + k0);
            nb1 = *(const float4*)(Bp + k0 + 4);
        }

#pragma unroll
        for (int kk = 0; kk < BK; kk++) {
            float4 a0 = *(const float4*)&As[cur][kk][ty * 8];
            float4 a1 = *(const float4*)&As[cur][kk][ty * 8 + 4];
            ulonglong2 bp0 = *(const ulonglong2*)&Bs[cur][kk][tx * 8];
            ulonglong2 bp1 = *(const ulonglong2*)&Bs[cur][kk][tx * 8 + 4];
            float a[8] = {a0.x, a0.y, a0.z, a0.w, a1.x, a1.y, a1.z, a1.w};
#pragma unroll
            for (int i = 0; i < 8; i++) {
                unsigned long long aa = pack2(a[i], a[i]);
                fma2(acc2[i][0], aa, bp0.x, acc2[i][0]);
                fma2(acc2[i][1], aa, bp0.y, acc2[i][1]);
                fma2(acc2[i][2], aa, bp1.x, acc2[i][2]);
                fma2(acc2[i][3], aa, bp1.y, acc2[i][3]);
            }
        }

        if (more) {
            int nxt = cur ^ 1;
            As[nxt][lk + 0][lrow] = na0.x; As[nxt][lk + 1][lrow] = na0.y;
            As[nxt][lk + 2][lrow] = na0.z; As[nxt][lk + 3][lrow] = na0.w;
            As[nxt][lk + 4][lrow] = na1.x; As[nxt][lk + 5][lrow] = na1.y;
            As[nxt][lk + 6][lrow] = na1.z; As[nxt][lk + 7][lrow] = na1.w;
            Bs[nxt][lk + 0][lrow] = nb0.x; Bs[nxt][lk + 1][lrow] = nb0.y;
            Bs[nxt][lk + 2][lrow] = nb0.z; Bs[nxt][lk + 3][lrow] = nb0.w;
            Bs[nxt][lk + 4][lrow] = nb1.x; Bs[nxt][lk + 5][lrow] = nb1.y;
            Bs[nxt][lk + 6][lrow] = nb1.z; Bs[nxt][lk + 7][lrow] = nb1.w;
            __syncthreads();
            cur = nxt;
        }
    }

#pragma unroll
    for (int i = 0; i < 8; i++) {
        float* Cp = C + (size_t)(blockIdx.y * 128 + ty * 8 + i) * N +
                    blockIdx.x * 128 + tx * 8;
        float2 c0 = unpack2(acc2[i][0]);
        float2 c1 = unpack2(acc2[i][1]);
        float2 c2 = unpack2(acc2[i][2]);
        float2 c3 = unpack2(acc2[i][3]);
        *(float4*)(Cp + 0) = make_float4(c0.x, c0.y, c1.x, c1.y);
        *(float4*)(Cp + 4) = make_float4(c2.x, c2.y, c3.x, c3.y);
    }
}

// ---------------------------------------------------------------------------
// Persistent recurrence: h_t = relu(xw_t + W_hh @ h_{t-1})
// Structure identical to passing R1/R4. Sync swap:
//   arrival:  bar.sync ; tid0: red.release.gpu.add  (release orders h-stores
//             of the whole block via bar.sync's CTA acq/rel chaining)
//   wait:     tid0 polls ld.acquire.gpu until count >= (t+1)*GBLK ; bar.sync
//             (acquire + bar orders all threads' subsequent h-loads)
// No threadfence, no ATOMG return trip. Dot product in f32x2 (proven in R4).
// ---------------------------------------------------------------------------
__global__ void __launch_bounds__(SCAN_TPB, 1) scan_kernel(
    const float* __restrict__ xw, const float* __restrict__ whh,
    float* __restrict__ y, float* __restrict__ hlast) {
    __shared__ float hbuf[HID];
    __shared__ float part[16][ROWS_PER_BLK];

    const int tid  = threadIdx.x;
    const int row  = tid & 15;
    const int kg   = tid >> 4;
    const int k0   = kg * KPT;
    const int rowG = blockIdx.x * ROWS_PER_BLK + row;
    const int warp = tid >> 5;
    const int lane = tid & 31;
    const int col  = blockIdx.x * ROWS_PER_BLK + tid;  // used when tid<16

    // W_hh slice -> registers as f32x2 pairs: wp[j] = w[2j], w[2j+1]
    unsigned long long wp[KPT / 2];
    {
        const float* wr = whh + (size_t)rowG * HID + k0;
#pragma unroll
        for (int i = 0; i < KPT / 4; i++) {
            ulonglong2 v = *(const ulonglong2*)(wr + i * 4);
            wp[2 * i]     = v.x;
            wp[2 * i + 1] = v.y;
        }
    }

    int p = 0;
    for (int t = 0; t < S_LEN; ++t) {
        // prefetch xw early (immutable within the layer)
        float xwv = 0.0f;
        if (tid < ROWS_PER_BLK) xwv = __ldg(&xw[(size_t)t * HID + col]);

        // broadcast h_{t-1}: one float4 per thread, L2 load
        float4 hv4 = __ldcg((const float4*)&g_h[p][tid * 4]);
        *(float4*)&hbuf[tid * 4] = hv4;
        __syncthreads();

        // dot product: 32 packed FFMA2 from register-resident W
        unsigned long long a0, a1, a2, a3;
        a0 = a1 = a2 = a3 = pack2(0.0f, 0.0f);
#pragma unroll
        for (int i = 0; i < KPT / 8; i++) {
            ulonglong2 h0 = *(const ulonglong2*)&hbuf[k0 + i * 8];
            ulonglong2 h1 = *(const ulonglong2*)&hbuf[k0 + i * 8 + 4];
            fma2(a0, wp[4 * i + 0], h0.x, a0);
            fma2(a1, wp[4 * i + 1], h0.y, a1);
            fma2(a2, wp[4 * i + 2], h1.x, a2);
            fma2(a3, wp[4 * i + 3], h1.y, a3);
        }
        float2 f0 = unpack2(a0), f1 = unpack2(a1);
        float2 f2 = unpack2(a2), f3 = unpack2(a3);
        float acc = ((f0.x + f0.y) + (f1.x + f1.y)) +
                    ((f2.x + f2.y) + (f3.x + f3.y));

        // combine the two k-groups living in one warp
        acc += __shfl_down_sync(0xffffffffu, acc, 16);
        if (lane < 16) part[warp][lane] = acc;
        __syncthreads();

        // final reduce + relu + publish (16 threads)
        if (tid < ROWS_PER_BLK) {
            float s = 0.f;
#pragma unroll
            for (int q = 0; q < 16; q++) s += part[q][tid];
            float hv = fmaxf(s + xwv, 0.0f);
            g_h[p ^ 1][col]          = hv;
            y[(size_t)t * HID + col] = hv;
            if (hlast != nullptr && t == S_LEN - 1) hlast[col] = hv;
        }
        __syncthreads();  // h-stores happen-before tid0's release arrival

        // grid barrier: release-reduction arrival + acquire poll
        if (tid == 0) {
            asm volatile("red.release.gpu.global.add.u32 [%0], %1;"
                         :: "l"(&g_bar), "r"(1u) : "memory");
            const unsigned target = (unsigned)(t + 1) * (unsigned)GBLK;
            unsigned v;
            do {
                asm volatile("ld.acquire.gpu.global.u32 %0, [%1];"
                             : "=r"(v) : "l"(&g_bar) : "memory");
            } while (v < target);
        }
        __syncthreads();  // acquire propagates to all threads via bar
        p ^= 1;
    }
}

// ---------------------------------------------------------------------------
// host launcher (graph-capturable: kernel launches only)
// ---------------------------------------------------------------------------
extern "C" void kernel_launch(void* const* d_in, const int* in_sizes, int n_in,
                              void* d_out, int out_size) {
    const float* x0  = (const float*)d_in[0];
    const float* wih = (const float*)d_in[1];
    const float* whh = (const float*)d_in[2];
    float* out = (float*)d_out;

    void *p_xw, *p_b0, *p_b1;
    cudaGetSymbolAddress(&p_xw, g_xw);
    cudaGetSymbolAddress(&p_b0, g_buf0);
    cudaGetSymbolAddress(&p_b1, g_buf1);
    float* bufs[2] = {(float*)p_b0, (float*)p_b1};

    float* hlast = (out_size >= S_LEN * HID + HID) ? out + (size_t)S_LEN * HID
                                                   : nullptr;

    const float* x = x0;
    dim3 ggrid(HID / 128, S_LEN / 128);
    for (int L = 0; L < NLAYERS; ++L) {
        reset_kernel<<<1, 512>>>();
        gemm_kernel<<<ggrid, 256>>>(x, wih + (size_t)L * HID * HID, (float*)p_xw);
        float* yout = (L == NLAYERS - 1) ? out : bufs[L & 1];
        scan_kernel<<<GBLK, SCAN_TPB>>>((const float*)p_xw,
                                        whh + (size_t)L * HID * HID, yout,
                                        (L == NLAYERS - 1) ? hlast : nullptr);
        x = yout;
    }
}